// round 7
// baseline (speedup 1.0000x reference)
#include <cuda_runtime.h>
#include <cuda_bf16.h>
#include <cfloat>
#include <math.h>
#include <stdint.h>

// ---------------- problem constants ----------------
static constexpr int kNH   = 16;
static constexpr int kS    = 512;
static constexpr int kH    = 2048;
static constexpr int kD    = 128;
static constexpr int kSC   = 8192;   // cache length
static constexpr int kTopK = 16;
static constexpr int kCand = 32;     // approx candidate pool per row
static constexpr int kQKVld = 3 * kH;          // 6144
static constexpr float kScale = 0.08838834764831845f;  // 1/sqrt(128)
static constexpr float kSimTh = 0.25f;
static constexpr float kNeg   = -1e30f;

// ---------------- scratch (__device__ globals; no allocation allowed) ----------------
__device__ __align__(16) float g_qkv[kS * kQKVld];                    // 12.6 MB
__device__ __align__(16) float g_sim[(size_t)kNH * kS * kSC];         // 268 MB (approx sims)
__device__ float g_topv[kNH * kS * kTopK];                            // exact vals
__device__ int   g_topi[kNH * kS * kTopK];                            // exact top-16 idx
__device__ int   g_cand[kNH * kS * kCand];                            // approx top-32 pool
__device__ __align__(16) float g_ctx[kS * kH];                        // 4 MB
__device__ __align__(16) float g_qn_f32[kNH * kS * kD];               // normalized q fp32
__device__ __align__(16) float g_kn_f32[(size_t)kNH * kSC * kD];      // normalized k fp32

// bf16 operands
__device__ __align__(16) __nv_bfloat16 g_hid_h[kS * kH];
__device__ __align__(16) __nv_bfloat16 g_hid_l[kS * kH];
__device__ __align__(16) __nv_bfloat16 g_wqkv_h[kQKVld * kH];
__device__ __align__(16) __nv_bfloat16 g_wqkv_l[kQKVld * kH];
__device__ __align__(16) __nv_bfloat16 g_wout_h[kH * kH];
__device__ __align__(16) __nv_bfloat16 g_wout_l[kH * kH];
__device__ __align__(16) __nv_bfloat16 g_qn_h[kNH * kS * kD];
__device__ __align__(16) __nv_bfloat16 g_kn_h[kNH * kSC * kD];
__device__ __align__(16) __nv_bfloat16 g_ctx_h[kS * kH];
__device__ __align__(16) __nv_bfloat16 g_ctx_l[kS * kH];

// ================= warp-mma helpers (compute_103-safe: sm_80 mma.sync) ==========
__device__ __forceinline__ uint32_t smem_u32(const void* p) {
    uint32_t a;
    asm("{ .reg .u64 t; cvta.to.shared.u64 t, %1; cvt.u32.u64 %0, t; }" : "=r"(a) : "l"(p));
    return a;
}
__device__ __forceinline__ void ldsm_x4(uint32_t* r, uint32_t addr) {
    asm volatile("ldmatrix.sync.aligned.m8n8.x4.shared.b16 {%0,%1,%2,%3}, [%4];"
                 : "=r"(r[0]), "=r"(r[1]), "=r"(r[2]), "=r"(r[3]) : "r"(addr));
}
__device__ __forceinline__ void ldsm_x2(uint32_t* r, uint32_t addr) {
    asm volatile("ldmatrix.sync.aligned.m8n8.x2.shared.b16 {%0,%1}, [%2];"
                 : "=r"(r[0]), "=r"(r[1]) : "r"(addr));
}
__device__ __forceinline__ void mma_bf16(float* d, const uint32_t* a, const uint32_t* b) {
    asm volatile(
        "mma.sync.aligned.m16n8k16.row.col.f32.bf16.bf16.f32 "
        "{%0,%1,%2,%3}, {%4,%5,%6,%7}, {%8,%9}, {%0,%1,%2,%3};"
        : "+f"(d[0]), "+f"(d[1]), "+f"(d[2]), "+f"(d[3])
        : "r"(a[0]), "r"(a[1]), "r"(a[2]), "r"(a[3]), "r"(b[0]), "r"(b[1]));
}

// ================= HMMA NT GEMM (templated #products) =================
static constexpr int kRowB   = 80;          // bytes per smem row (conflict-free ldmatrix)
static constexpr int kMatB   = 128 * kRowB; // 10240

template<int NPROD>
__global__ void __launch_bounds__(256, 1)
mma_gemm(const __nv_bfloat16* __restrict__ Ah, const __nv_bfloat16* __restrict__ Al,
         const __nv_bfloat16* __restrict__ Bh, const __nv_bfloat16* __restrict__ Bl,
         float* __restrict__ C,
         int lda, int ldb, int ldc,
         long long aS, long long bS, long long cS, int K)
{
    constexpr int AH = 0;
    constexpr int AL = kMatB;
    constexpr int BH = (NPROD == 3) ? 2 * kMatB : kMatB;
    constexpr int BL = 3 * kMatB;
    constexpr int STAGE = ((NPROD == 3) ? 4 : 2) * kMatB;

    extern __shared__ char smem[];
    const uint32_t sb = smem_u32(smem);
    const int tid  = threadIdx.x;
    const int lane = tid & 31;
    const int warp = tid >> 5;
    const int wy = warp >> 2;
    const int wx = warp & 3;
    const int m0 = blockIdx.y * 128, n0 = blockIdx.x * 128, z = blockIdx.z;

    const __nv_bfloat16* pAh = Ah + (long long)z * aS;
    const __nv_bfloat16* pAl = (NPROD == 3) ? Al + (long long)z * aS : nullptr;
    const __nv_bfloat16* pBh = Bh + (long long)z * bS;
    const __nv_bfloat16* pBl = (NPROD == 3) ? Bl + (long long)z * bS : nullptr;

    float acc[4][4][4];
#pragma unroll
    for (int i = 0; i < 4; i++)
#pragma unroll
        for (int j = 0; j < 4; j++)
#pragma unroll
            for (int e = 0; e < 4; e++) acc[i][j][e] = 0.f;

    const int r0s = tid >> 2, c0s = tid & 3;
    const int r1s = (tid + 256) >> 2, c1s = tid & 3;
    const int nCh = K >> 5;

    auto stageStore = [&](int c) {
        const int k0 = c << 5;
        char* stp = smem + (c & 1) * STAGE;
        {
            const long long ga = (long long)(m0 + r0s) * lda + k0 + c0s * 8;
            const long long gb = (long long)(n0 + r0s) * ldb + k0 + c0s * 8;
            const int so = r0s * kRowB + c0s * 16;
            *(uint4*)(stp + AH + so) = *(const uint4*)(pAh + ga);
            *(uint4*)(stp + BH + so) = *(const uint4*)(pBh + gb);
            if (NPROD == 3) {
                *(uint4*)(stp + AL + so) = *(const uint4*)(pAl + ga);
                *(uint4*)(stp + BL + so) = *(const uint4*)(pBl + gb);
            }
        }
        {
            const long long ga = (long long)(m0 + r1s) * lda + k0 + c1s * 8;
            const long long gb = (long long)(n0 + r1s) * ldb + k0 + c1s * 8;
            const int so = r1s * kRowB + c1s * 16;
            *(uint4*)(stp + AH + so) = *(const uint4*)(pAh + ga);
            *(uint4*)(stp + BH + so) = *(const uint4*)(pBh + gb);
            if (NPROD == 3) {
                *(uint4*)(stp + AL + so) = *(const uint4*)(pAl + ga);
                *(uint4*)(stp + BL + so) = *(const uint4*)(pBl + gb);
            }
        }
    };

    stageStore(0);
    __syncthreads();

    const int laneA_row = (lane & 15);
    const int laneA_cb  = (lane >> 4) * 16;
    const int laneB_row = (lane & 7);
    const int laneB_cb  = ((lane >> 3) & 1) * 16;

    for (int c = 0; c < nCh; c++) {
        if (c + 1 < nCh) stageStore(c + 1);

        const uint32_t stb = sb + (c & 1) * STAGE;
#pragma unroll
        for (int kf = 0; kf < 2; kf++) {
            const int kb = kf * 32;
            uint32_t a_h[4][4], a_l[4][4], b_h[4][2], b_l[4][2];
#pragma unroll
            for (int i = 0; i < 4; i++) {
                const uint32_t ra = stb + (uint32_t)((wy * 64 + i * 16 + laneA_row) * kRowB + kb + laneA_cb);
                ldsm_x4(a_h[i], ra + AH);
                if (NPROD == 3) ldsm_x4(a_l[i], ra + AL);
            }
#pragma unroll
            for (int j = 0; j < 4; j++) {
                const uint32_t rb = stb + (uint32_t)((wx * 32 + j * 8 + laneB_row) * kRowB + kb + laneB_cb);
                ldsm_x2(b_h[j], rb + BH);
                if (NPROD == 3) ldsm_x2(b_l[j], rb + BL);
            }
#pragma unroll
            for (int i = 0; i < 4; i++)
#pragma unroll
                for (int j = 0; j < 4; j++) {
                    mma_bf16(acc[i][j], a_h[i], b_h[j]);
                    if (NPROD == 3) {
                        mma_bf16(acc[i][j], a_h[i], b_l[j]);
                        mma_bf16(acc[i][j], a_l[i], b_h[j]);
                    }
                }
        }
        __syncthreads();
    }

    float* Cb = C + (long long)z * cS;
#pragma unroll
    for (int i = 0; i < 4; i++) {
        const int rr = m0 + wy * 64 + i * 16 + (lane >> 2);
#pragma unroll
        for (int j = 0; j < 4; j++) {
            const int cc = n0 + wx * 32 + j * 8 + (lane & 3) * 2;
            float2 v0; v0.x = acc[i][j][0]; v0.y = acc[i][j][1];
            float2 v1; v1.x = acc[i][j][2]; v1.y = acc[i][j][3];
            *(float2*)(Cb + (long long)rr * ldc + cc)       = v0;
            *(float2*)(Cb + (long long)(rr + 8) * ldc + cc) = v1;
        }
    }
}

// ================= fp32 SGEMM (exact path for Q projection) =================
__global__ void __launch_bounds__(256, 2)
sgemm_nt(const float* __restrict__ A, int lda,
         const float* __restrict__ B, int ldb,
         float* __restrict__ C, int ldc, int K)
{
    __shared__ float As[16][128];
    __shared__ float Bs[16][128];

    const int tid = threadIdx.x;
    const int m0  = blockIdx.y * 128;
    const int n0  = blockIdx.x * 128;

    const int lr = tid >> 2;
    const int lc = (tid & 3) << 2;
    const int tx = tid & 15;
    const int ty = tid >> 4;

    float acc[8][8];
#pragma unroll
    for (int i = 0; i < 8; i++)
#pragma unroll
        for (int j = 0; j < 8; j++) acc[i][j] = 0.f;

    for (int k0 = 0; k0 < K; k0 += 16) {
        float4 a0 = *(const float4*)(A + (long long)(m0 + lr)      * lda + k0 + lc);
        float4 a1 = *(const float4*)(A + (long long)(m0 + lr + 64) * lda + k0 + lc);
        float4 b0 = *(const float4*)(B + (long long)(n0 + lr)      * ldb + k0 + lc);
        float4 b1 = *(const float4*)(B + (long long)(n0 + lr + 64) * ldb + k0 + lc);
        __syncthreads();
        As[lc + 0][lr] = a0.x; As[lc + 1][lr] = a0.y; As[lc + 2][lr] = a0.z; As[lc + 3][lr] = a0.w;
        As[lc + 0][lr + 64] = a1.x; As[lc + 1][lr + 64] = a1.y; As[lc + 2][lr + 64] = a1.z; As[lc + 3][lr + 64] = a1.w;
        Bs[lc + 0][lr] = b0.x; Bs[lc + 1][lr] = b0.y; Bs[lc + 2][lr] = b0.z; Bs[lc + 3][lr] = b0.w;
        Bs[lc + 0][lr + 64] = b1.x; Bs[lc + 1][lr + 64] = b1.y; Bs[lc + 2][lr + 64] = b1.z; Bs[lc + 3][lr + 64] = b1.w;
        __syncthreads();
#pragma unroll
        for (int kk = 0; kk < 16; kk++) {
            float4 av0 = *(const float4*)&As[kk][ty * 8];
            float4 av1 = *(const float4*)&As[kk][ty * 8 + 4];
            float4 bv0 = *(const float4*)&Bs[kk][tx * 8];
            float4 bv1 = *(const float4*)&Bs[kk][tx * 8 + 4];
            float a[8] = {av0.x, av0.y, av0.z, av0.w, av1.x, av1.y, av1.z, av1.w};
            float b[8] = {bv0.x, bv0.y, bv0.z, bv0.w, bv1.x, bv1.y, bv1.z, bv1.w};
#pragma unroll
            for (int i = 0; i < 8; i++)
#pragma unroll
                for (int j = 0; j < 8; j++) acc[i][j] = fmaf(a[i], b[j], acc[i][j]);
        }
    }

#pragma unroll
    for (int i = 0; i < 8; i++) {
        float* crow = C + (long long)(m0 + ty * 8 + i) * ldc + n0 + tx * 8;
#pragma unroll
        for (int j = 0; j < 8; j++) crow[j] = acc[i][j];
    }
}

// ================= splits =================
__global__ void split_kernel(const float* __restrict__ src,
                             __nv_bfloat16* __restrict__ hi,
                             __nv_bfloat16* __restrict__ lo, int n4)
{
    const int i = blockIdx.x * blockDim.x + threadIdx.x;
    if (i >= n4) return;
    const float4 v = ((const float4*)src)[i];
    __nv_bfloat16 h0 = __float2bfloat16(v.x);
    __nv_bfloat16 h1 = __float2bfloat16(v.y);
    __nv_bfloat16 h2 = __float2bfloat16(v.z);
    __nv_bfloat16 h3 = __float2bfloat16(v.w);
    __nv_bfloat162 H0; H0.x = h0; H0.y = h1;
    __nv_bfloat162 H1; H1.x = h2; H1.y = h3;
    __nv_bfloat162 L0, L1;
    L0.x = __float2bfloat16(v.x - __bfloat162float(h0));
    L0.y = __float2bfloat16(v.y - __bfloat162float(h1));
    L1.x = __float2bfloat16(v.z - __bfloat162float(h2));
    L1.y = __float2bfloat16(v.w - __bfloat162float(h3));
    ((__nv_bfloat162*)hi)[2 * i]     = H0;
    ((__nv_bfloat162*)hi)[2 * i + 1] = H1;
    ((__nv_bfloat162*)lo)[2 * i]     = L0;
    ((__nv_bfloat162*)lo)[2 * i + 1] = L1;
}

__global__ void qsplit_kernel()
{
    const int gw   = (blockIdx.x * blockDim.x + threadIdx.x) >> 5;
    const int lane = threadIdx.x & 31;
    if (gw >= kNH * kS) return;
    const int h = gw >> 9;
    const int q = gw & 511;
    float4 v = *(const float4*)(g_qkv + (long long)q * kQKVld + h * kD + lane * 4);
    float s = v.x * v.x + v.y * v.y + v.z * v.z + v.w * v.w;
#pragma unroll
    for (int o = 16; o > 0; o >>= 1) s += __shfl_xor_sync(0xffffffffu, s, o);
    const float inv = rsqrtf(s);
    v.x *= inv; v.y *= inv; v.z *= inv; v.w *= inv;
    const long long base = (long long)gw * kD + lane * 4;
    *(float4*)(g_qn_f32 + base) = v;
    __nv_bfloat162 H0, H1;
    H0.x = __float2bfloat16(v.x); H0.y = __float2bfloat16(v.y);
    H1.x = __float2bfloat16(v.z); H1.y = __float2bfloat16(v.w);
    *(__nv_bfloat162*)(g_qn_h + base)     = H0;
    *(__nv_bfloat162*)(g_qn_h + base + 2) = H1;
}

__global__ void ksplit_kernel(const float* __restrict__ kc)
{
    const int gw   = (blockIdx.x * blockDim.x + threadIdx.x) >> 5;
    const int lane = threadIdx.x & 31;
    if (gw >= kNH * kSC) return;
    float4 v = *(const float4*)(kc + (long long)gw * kD + lane * 4);
    float s = v.x * v.x + v.y * v.y + v.z * v.z + v.w * v.w;
#pragma unroll
    for (int o = 16; o > 0; o >>= 1) s += __shfl_xor_sync(0xffffffffu, s, o);
    const float inv = rsqrtf(s);
    v.x *= inv; v.y *= inv; v.z *= inv; v.w *= inv;
    const long long base = (long long)gw * kD + lane * 4;
    *(float4*)(g_kn_f32 + base) = v;
    __nv_bfloat162 H0, H1;
    H0.x = __float2bfloat16(v.x); H0.y = __float2bfloat16(v.y);
    H1.x = __float2bfloat16(v.z); H1.y = __float2bfloat16(v.w);
    *(__nv_bfloat162*)(g_kn_h + base)     = H0;
    *(__nv_bfloat162*)(g_kn_h + base + 2) = H1;
}

// ---------------- per-(h,q) approx top-32 over 8192 sims ----------------
__global__ void __launch_bounds__(256)
topk_kernel()
{
    const long long row = blockIdx.x;
    const float* sim = g_sim + row * kSC;
    const int tid = threadIdx.x;
    const int lane = tid & 31;
    const int w = tid >> 5;

    float v[32];
#pragma unroll
    for (int i = 0; i < 32; i++) v[i] = sim[tid + (i << 8)];

    __shared__ float wv[8];
    __shared__ int   wi[8];
    __shared__ int   bi;

    for (int r = 0; r < kCand; r++) {
        float mv = -FLT_MAX; int mi = 0x7fffffff;
#pragma unroll
        for (int i = 0; i < 32; i++) {
            if (v[i] > mv) { mv = v[i]; mi = tid + (i << 8); }
        }
#pragma unroll
        for (int o = 16; o > 0; o >>= 1) {
            float ov = __shfl_down_sync(0xffffffffu, mv, o);
            int   oi = __shfl_down_sync(0xffffffffu, mi, o);
            if (ov > mv || (ov == mv && oi < mi)) { mv = ov; mi = oi; }
        }
        if (lane == 0) { wv[w] = mv; wi[w] = mi; }
        __syncthreads();
        if (tid == 0) {
            float m = wv[0]; int ix = wi[0];
#pragma unroll
            for (int k = 1; k < 8; k++)
                if (wv[k] > m || (wv[k] == m && wi[k] < ix)) { m = wv[k]; ix = wi[k]; }
            bi = ix;
            g_cand[row * kCand + r] = ix;
        }
        __syncthreads();
        const int sel = bi;
        if ((sel & 255) == tid) v[sel >> 8] = -FLT_MAX;
    }
}

// ---------------- exact rescore of 32 candidates -> exact top-16 ----------------
__global__ void __launch_bounds__(256)
rescore_kernel()
{
    const int gw   = (blockIdx.x * blockDim.x + threadIdx.x) >> 5;
    const int lane = threadIdx.x & 31;
    if (gw >= kNH * kS) return;
    const int h = gw >> 9;

    const float4 qv = *(const float4*)(g_qn_f32 + (long long)gw * kD + lane * 4);
    int   myidx = g_cand[gw * kCand + lane];
    float myval = -FLT_MAX;

    for (int c = 0; c < kCand; c++) {
        const int idx = __shfl_sync(0xffffffffu, myidx, c);
        const float4 kv = *(const float4*)(g_kn_f32 + ((long long)h * kSC + idx) * kD + lane * 4);
        float p = qv.x * kv.x + qv.y * kv.y + qv.z * kv.z + qv.w * kv.w;
#pragma unroll
        for (int o = 16; o > 0; o >>= 1) p += __shfl_xor_sync(0xffffffffu, p, o);
        if (lane == c) myval = p;
    }

    for (int r = 0; r < kTopK; r++) {
        float v = myval; int ix = myidx;
#pragma unroll
        for (int o = 16; o > 0; o >>= 1) {
            float ov = __shfl_xor_sync(0xffffffffu, v, o);
            int   oi = __shfl_xor_sync(0xffffffffu, ix, o);
            if (ov > v || (ov == v && oi < ix)) { v = ov; ix = oi; }
        }
        if (lane == 0) {
            g_topv[gw * kTopK + r] = v;
            g_topi[gw * kTopK + r] = ix;
        }
        if (myidx == ix) myval = -FLT_MAX;
    }
}

// ---------------- tiled attention: 32 queries per block ----------------
static constexpr int kQB = 32;     // queries per block
static constexpr int kKT = 64;     // key tile
static constexpr int kPsLd = 545;  // score row stride (floats), odd mod 32

struct AttnSmem {
    float Qs[kQB * kD];         // 16 KB
    float Ps[kQB * kPsLd];      // 69.8 KB  [16 ext | 512 local]
    float KV[kKT * kD];         // 32 KB (K tiles, then V tiles)
    int   sidx[kQB * 16];
    float tv[kQB * 16];
};

__global__ void __launch_bounds__(256, 1)
attn2_kernel(const float* __restrict__ kc, const float* __restrict__ vc,
             const float* __restrict__ bias)
{
    extern __shared__ char sraw[];
    AttnSmem& sm = *reinterpret_cast<AttnSmem*>(sraw);
    const int h   = blockIdx.y;
    const int qb  = (int)gridDim.x - 1 - (int)blockIdx.x;   // heavy blocks first
    const int q0  = qb * kQB;
    const int kEnd = q0 + kQB;                              // max causal key + 1
    const int nT  = (kEnd + kKT - 1) / kKT;
    const int tid = threadIdx.x, lane = tid & 31, w = tid >> 5;

    // stage Q rows + top-k metadata
    for (int i = tid; i < kQB * kD / 4; i += 256) {
        const int r = i >> 5, c = (i & 31) << 2;
        *(float4*)&sm.Qs[r * kD + c] =
            *(const float4*)&g_qkv[(long long)(q0 + r) * kQKVld + h * kD + c];
    }
    for (int i = tid; i < kQB * 16; i += 256) {
        const long long rowhq = (long long)h * kS + q0 + (i >> 4);
        sm.sidx[i] = g_topi[rowhq * 16 + (i & 15)];
        sm.tv[i]   = g_topv[rowhq * 16 + (i & 15)];
    }
    __syncthreads();

    // ext scores: 32q x 16 slots, one warp-dot each
    for (int e = w; e < kQB * 16; e += 8) {
        const int r = e >> 4, j = e & 15;
        if (sm.tv[e] > kSimTh) {
            const float* kp = kc + ((long long)h * kSC + sm.sidx[e]) * kD;
            const float4 kv = *(const float4*)(kp + lane * 4);
            const float4 qv = *(const float4*)(sm.Qs + r * kD + lane * 4);
            float p = qv.x * kv.x + qv.y * kv.y + qv.z * kv.z + qv.w * kv.w;
#pragma unroll
            for (int o = 16; o > 0; o >>= 1) p += __shfl_down_sync(0xffffffffu, p, o);
            if (lane == 0) sm.Ps[r * kPsLd + j] = p * kScale;
        } else if (lane == 0) {
            sm.Ps[r * kPsLd + j] = kNeg;
        }
    }

    // local causal scores by K tiles
    for (int t = 0; t < nT; t++) {
        const int kt0 = t * kKT;
        __syncthreads();
        for (int i = tid; i < kKT * kD / 4; i += 256) {
            const int r = i >> 5, c = (i & 31) << 2;
            *(float4*)&sm.KV[r * kD + c] =
                *(const float4*)&g_qkv[(long long)(kt0 + r) * kQKVld + kH + h * kD + c];
        }
        __syncthreads();
#pragma unroll
        for (int kk2 = 0; kk2 < 8; kk2++) {
            const int kg = kt0 + w * 8 + kk2;
            if (kg >= kEnd) break;
            const float4 kv = *(const float4*)(sm.KV + (w * 8 + kk2) * kD + lane * 4);
            for (int r = 0; r < kQB; r++) {
                const int qg = q0 + r;
                if (kg <= qg) {
                    const float4 qv = *(const float4*)(sm.Qs + r * kD + lane * 4);
                    float p = qv.x * kv.x + qv.y * kv.y + qv.z * kv.z + qv.w * kv.w;
#pragma unroll
                    for (int o = 16; o > 0; o >>= 1) p += __shfl_down_sync(0xffffffffu, p, o);
                    if (lane == 0)
                        sm.Ps[r * kPsLd + 16 + kg] =
                            p * kScale + bias[((long long)h * kS + qg) * kS + kg];
                } else if (lane == 0) {
                    sm.Ps[r * kPsLd + 16 + kg] = kNeg;
                }
            }
        }
    }
    __syncthreads();

    // softmax: warp w owns queries 4w..4w+3; normalize probs in place
    const int n = 16 + kEnd;
    for (int rr = 0; rr < 4; rr++) {
        float* row = sm.Ps + (w * 4 + rr) * kPsLd;
        float m = -FLT_MAX;
        for (int j = lane; j < n; j += 32) m = fmaxf(m, row[j]);
#pragma unroll
        for (int o = 16; o > 0; o >>= 1) m = fmaxf(m, __shfl_xor_sync(0xffffffffu, m, o));
        float ss = 0.f;
        for (int j = lane; j < n; j += 32) {
            const float e = __expf(row[j] - m);
            row[j] = e;
            ss += e;
        }
#pragma unroll
        for (int o = 16; o > 0; o >>= 1) ss += __shfl_xor_sync(0xffffffffu, ss, o);
        const float inv = 1.f / ss;
        for (int j = lane; j < n; j += 32) row[j] *= inv;
    }
    __syncthreads();

    // context: thread owns (query r, 16 dims at dg)
    const int r  = tid >> 3;
    const int dg = (tid & 7) * 16;
    float acc[16];
#pragma unroll
    for (int i = 0; i < 16; i++) acc[i] = 0.f;

    // ext V gather
    for (int j = 0; j < 16; j++) {
        const float p = sm.Ps[r * kPsLd + j];
        if (p > 0.f) {
            const float* vp = vc + ((long long)h * kSC + sm.sidx[r * 16 + j]) * kD + dg;
#pragma unroll
            for (int i = 0; i < 4; i++) {
                const float4 v = ((const float4*)vp)[i];
                acc[4 * i + 0] = fmaf(p, v.x, acc[4 * i + 0]);
                acc[4 * i + 1] = fmaf(p, v.y, acc[4 * i + 1]);
                acc[4 * i + 2] = fmaf(p, v.z, acc[4 * i + 2]);
                acc[4 * i + 3] = fmaf(p, v.w, acc[4 * i + 3]);
            }
        }
    }

    // local V tiles
    for (int t = 0; t < nT; t++) {
        const int kt0 = t * kKT;
        __syncthreads();
        for (int i = tid; i < kKT * kD / 4; i += 256) {
            const int rr = i >> 5, c = (i & 31) << 2;
            *(float4*)&sm.KV[rr * kD + c] =
                *(const float4*)&g_qkv[(long long)(kt0 + rr) * kQKVld + 2 * kH + h * kD + c];
        }
        __syncthreads();
        const int kmax = min(kKT, q0 + r + 1 - kt0);
        for (int kk = 0; kk < kmax; kk++) {
            const float p = sm.Ps[r * kPsLd + 16 + kt0 + kk];
            const float* vp = sm.KV + kk * kD + dg;
#pragma unroll
            for (int i = 0; i < 4; i++) {
                const float4 v = ((const float4*)vp)[i];
                acc[4 * i + 0] = fmaf(p, v.x, acc[4 * i + 0]);
                acc[4 * i + 1] = fmaf(p, v.y, acc[4 * i + 1]);
                acc[4 * i + 2] = fmaf(p, v.z, acc[4 * i + 2]);
                acc[4 * i + 3] = fmaf(p, v.w, acc[4 * i + 3]);
            }
        }
    }

    float* op = g_ctx + (long long)(q0 + r) * kH + h * kD + dg;
#pragma unroll
    for (int i = 0; i < 4; i++) {
        float4 v;
        v.x = acc[4 * i + 0]; v.y = acc[4 * i + 1];
        v.z = acc[4 * i + 2]; v.w = acc[4 * i + 3];
        ((float4*)op)[i] = v;
    }
}

// ---------------- launcher ----------------
extern "C" void kernel_launch(void* const* d_in, const int* in_sizes, int n_in,
                              void* d_out, int out_size)
{
    const float* hidden = (const float*)d_in[0];
    const float* Wqkv   = (const float*)d_in[1];
    const float* Wout   = (const float*)d_in[2];
    const float* kc     = (const float*)d_in[3];
    const float* vc     = (const float*)d_in[4];
    const float* bias   = (const float*)d_in[5];
    float* out = (float*)d_out;

    float *p_qkv, *p_sim, *p_ctx;
    cudaGetSymbolAddress((void**)&p_qkv,  g_qkv);
    cudaGetSymbolAddress((void**)&p_sim,  g_sim);
    cudaGetSymbolAddress((void**)&p_ctx,  g_ctx);
    __nv_bfloat16 *p_hid_h, *p_hid_l, *p_wqkv_h, *p_wqkv_l, *p_wout_h, *p_wout_l;
    __nv_bfloat16 *p_qn_h, *p_kn_h, *p_ctx_h, *p_ctx_l;
    cudaGetSymbolAddress((void**)&p_hid_h,  g_hid_h);
    cudaGetSymbolAddress((void**)&p_hid_l,  g_hid_l);
    cudaGetSymbolAddress((void**)&p_wqkv_h, g_wqkv_h);
    cudaGetSymbolAddress((void**)&p_wqkv_l, g_wqkv_l);
    cudaGetSymbolAddress((void**)&p_wout_h, g_wout_h);
    cudaGetSymbolAddress((void**)&p_wout_l, g_wout_l);
    cudaGetSymbolAddress((void**)&p_qn_h,   g_qn_h);
    cudaGetSymbolAddress((void**)&p_kn_h,   g_kn_h);
    cudaGetSymbolAddress((void**)&p_ctx_h,  g_ctx_h);
    cudaGetSymbolAddress((void**)&p_ctx_l,  g_ctx_l);

    cudaFuncSetAttribute(mma_gemm<3>, cudaFuncAttributeMaxDynamicSharedMemorySize, 2 * 4 * kMatB);
    cudaFuncSetAttribute(mma_gemm<1>, cudaFuncAttributeMaxDynamicSharedMemorySize, 2 * 2 * kMatB);
    cudaFuncSetAttribute(attn2_kernel, cudaFuncAttributeMaxDynamicSharedMemorySize, (int)sizeof(AttnSmem));

    // 1. splits of weights / hidden + normalized k cache (fp32 + bf16)
    split_kernel<<<(kQKVld * kH / 4 + 255) / 256, 256>>>(Wqkv, p_wqkv_h, p_wqkv_l, kQKVld * kH / 4);
    split_kernel<<<(kH * kH / 4 + 255) / 256, 256>>>(Wout, p_wout_h, p_wout_l, kH * kH / 4);
    split_kernel<<<(kS * kH / 4 + 255) / 256, 256>>>(hidden, p_hid_h, p_hid_l, kS * kH / 4);
    ksplit_kernel<<<(kNH * kSC * 32) / 256, 256>>>(kc);

    // 2a. Q projection EXACT fp32
    sgemm_nt<<<dim3(kH / 128, kS / 128), 256>>>(hidden, kH, Wqkv, kH, p_qkv, kQKVld, kH);

    // 2b. K,V projections (HMMA 3-prod)
    mma_gemm<3><<<dim3(4096 / 128, kS / 128, 1), 256, 2 * 4 * kMatB>>>(
        p_hid_h, p_hid_l, p_wqkv_h + (size_t)2048 * kH, p_wqkv_l + (size_t)2048 * kH,
        p_qkv + 2048, kH, kH, kQKVld, 0, 0, 0, kH);

    // 3. normalized q (fp32 + bf16)
    qsplit_kernel<<<(kNH * kS * 32) / 256, 256>>>();

    // 4. approx cosine-sim GEMM (HMMA 1-prod bf16)
    mma_gemm<1><<<dim3(kSC / 128, kS / 128, kNH), 256, 2 * 2 * kMatB>>>(
        p_qn_h, nullptr, p_kn_h, nullptr, p_sim,
        kD, kD, kSC,
        (long long)kS * kD, (long long)kSC * kD, (long long)kS * kSC, kD);

    // 5. approx top-32 candidate pool per (h,q)
    topk_kernel<<<kNH * kS, 256>>>();

    // 6. exact fp32 rescore -> exact top-16
    rescore_kernel<<<(kNH * kS * 32 + 255) / 256, 256>>>();

    // 7. tiled attention (32 queries/block) -> g_ctx
    attn2_kernel<<<dim3(kS / kQB, kNH), 256, sizeof(AttnSmem)>>>(kc, vc, bias);

    // 8. ctx split + output projection (HMMA 3-prod)
    split_kernel<<<(kS * kH / 4 + 255) / 256, 256>>>(p_ctx, p_ctx_h, p_ctx_l, kS * kH / 4);
    mma_gemm<3><<<dim3(kH / 128, kS / 128, 1), 256, 2 * 4 * kMatB>>>(
        p_ctx_h, p_ctx_l, p_wout_h, p_wout_l, out,
        kH, kH, kH, 0, 0, 0, kH);
}

// round 8
// speedup vs baseline: 2.0679x; 2.0679x over previous
#include <cuda_runtime.h>
#include <cuda_bf16.h>
#include <cfloat>
#include <math.h>
#include <stdint.h>
#include <string.h>

// ---------------- problem constants ----------------
static constexpr int kNH   = 16;
static constexpr int kS    = 512;
static constexpr int kH    = 2048;
static constexpr int kD    = 128;
static constexpr int kSC   = 8192;   // cache length
static constexpr int kTopK = 16;
static constexpr int kCand = 32;     // approx candidate pool per row
static constexpr int kQKVld = 3 * kH;          // 6144
static constexpr float kScale = 0.08838834764831845f;  // 1/sqrt(128)
static constexpr float kSimTh = 0.25f;
static constexpr float kNeg   = -1e30f;

// ---------------- scratch (__device__ globals; no allocation allowed) ----------------
__device__ __align__(16) float g_qkv[kS * kQKVld];                    // 12.6 MB
__device__ __align__(16) uint16_t g_simkey[(size_t)kNH * kS * kSC];   // 134 MB monotone keys
__device__ float g_topv[kNH * kS * kTopK];                            // exact vals
__device__ int   g_topi[kNH * kS * kTopK];                            // exact top-16 idx
__device__ int   g_cand[kNH * kS * kCand];                            // approx top-32 pool
__device__ __align__(16) float g_ctx[kS * kH];                        // 4 MB
__device__ __align__(16) float g_qn_f32[kNH * kS * kD];               // normalized q fp32
__device__ __align__(16) float g_kn_f32[(size_t)kNH * kSC * kD];      // normalized k fp32

// bf16 operands
__device__ __align__(16) __nv_bfloat16 g_hid_h[kS * kH];
__device__ __align__(16) __nv_bfloat16 g_hid_l[kS * kH];
__device__ __align__(16) __nv_bfloat16 g_wqkv_h[kQKVld * kH];
__device__ __align__(16) __nv_bfloat16 g_wqkv_l[kQKVld * kH];
__device__ __align__(16) __nv_bfloat16 g_wout_h[kH * kH];
__device__ __align__(16) __nv_bfloat16 g_wout_l[kH * kH];
__device__ __align__(16) __nv_bfloat16 g_qn_h[kNH * kS * kD];
__device__ __align__(16) __nv_bfloat16 g_kn_h[kNH * kSC * kD];
__device__ __align__(16) __nv_bfloat16 g_ctx_h[kS * kH];
__device__ __align__(16) __nv_bfloat16 g_ctx_l[kS * kH];

// ================= warp-mma helpers (compute_103-safe: sm_80 mma.sync) ==========
__device__ __forceinline__ uint32_t smem_u32(const void* p) {
    uint32_t a;
    asm("{ .reg .u64 t; cvta.to.shared.u64 t, %1; cvt.u32.u64 %0, t; }" : "=r"(a) : "l"(p));
    return a;
}
__device__ __forceinline__ void ldsm_x4(uint32_t* r, uint32_t addr) {
    asm volatile("ldmatrix.sync.aligned.m8n8.x4.shared.b16 {%0,%1,%2,%3}, [%4];"
                 : "=r"(r[0]), "=r"(r[1]), "=r"(r[2]), "=r"(r[3]) : "r"(addr));
}
__device__ __forceinline__ void ldsm_x2(uint32_t* r, uint32_t addr) {
    asm volatile("ldmatrix.sync.aligned.m8n8.x2.shared.b16 {%0,%1}, [%2];"
                 : "=r"(r[0]), "=r"(r[1]) : "r"(addr));
}
__device__ __forceinline__ void mma_bf16(float* d, const uint32_t* a, const uint32_t* b) {
    asm volatile(
        "mma.sync.aligned.m16n8k16.row.col.f32.bf16.bf16.f32 "
        "{%0,%1,%2,%3}, {%4,%5,%6,%7}, {%8,%9}, {%0,%1,%2,%3};"
        : "+f"(d[0]), "+f"(d[1]), "+f"(d[2]), "+f"(d[3])
        : "r"(a[0]), "r"(a[1]), "r"(a[2]), "r"(a[3]), "r"(b[0]), "r"(b[1]));
}
// order-preserving uint16 key of a float (via bf16)
__device__ __forceinline__ uint16_t bf16_mono(float x) {
    __nv_bfloat16 b = __float2bfloat16(x);
    uint16_t u;
    memcpy(&u, &b, 2);
    return (u & 0x8000) ? (uint16_t)(~u) : (uint16_t)(u | 0x8000);
}

// ================= HMMA NT GEMM (NPROD products; fp32 or key16 output) ==========
static constexpr int kRowB   = 80;          // bytes per smem row (conflict-free ldmatrix)
static constexpr int kMatB   = 128 * kRowB; // 10240

template<int NPROD, bool KEY16>
__global__ void __launch_bounds__(256, 1)
mma_gemm(const __nv_bfloat16* __restrict__ Ah, const __nv_bfloat16* __restrict__ Al,
         const __nv_bfloat16* __restrict__ Bh, const __nv_bfloat16* __restrict__ Bl,
         void* __restrict__ Cv,
         int lda, int ldb, int ldc,
         long long aS, long long bS, long long cS, int K)
{
    constexpr int AH = 0;
    constexpr int AL = kMatB;
    constexpr int BH = (NPROD == 3) ? 2 * kMatB : kMatB;
    constexpr int BL = 3 * kMatB;
    constexpr int STAGE = ((NPROD == 3) ? 4 : 2) * kMatB;

    extern __shared__ char smem[];
    const uint32_t sb = smem_u32(smem);
    const int tid  = threadIdx.x;
    const int lane = tid & 31;
    const int warp = tid >> 5;
    const int wy = warp >> 2;
    const int wx = warp & 3;
    const int m0 = blockIdx.y * 128, n0 = blockIdx.x * 128, z = blockIdx.z;

    const __nv_bfloat16* pAh = Ah + (long long)z * aS;
    const __nv_bfloat16* pAl = (NPROD == 3) ? Al + (long long)z * aS : nullptr;
    const __nv_bfloat16* pBh = Bh + (long long)z * bS;
    const __nv_bfloat16* pBl = (NPROD == 3) ? Bl + (long long)z * bS : nullptr;

    float acc[4][4][4];
#pragma unroll
    for (int i = 0; i < 4; i++)
#pragma unroll
        for (int j = 0; j < 4; j++)
#pragma unroll
            for (int e = 0; e < 4; e++) acc[i][j][e] = 0.f;

    const int r0s = tid >> 2, c0s = tid & 3;
    const int r1s = (tid + 256) >> 2, c1s = tid & 3;
    const int nCh = K >> 5;

    auto stageStore = [&](int c) {
        const int k0 = c << 5;
        char* stp = smem + (c & 1) * STAGE;
        {
            const long long ga = (long long)(m0 + r0s) * lda + k0 + c0s * 8;
            const long long gb = (long long)(n0 + r0s) * ldb + k0 + c0s * 8;
            const int so = r0s * kRowB + c0s * 16;
            *(uint4*)(stp + AH + so) = *(const uint4*)(pAh + ga);
            *(uint4*)(stp + BH + so) = *(const uint4*)(pBh + gb);
            if (NPROD == 3) {
                *(uint4*)(stp + AL + so) = *(const uint4*)(pAl + ga);
                *(uint4*)(stp + BL + so) = *(const uint4*)(pBl + gb);
            }
        }
        {
            const long long ga = (long long)(m0 + r1s) * lda + k0 + c1s * 8;
            const long long gb = (long long)(n0 + r1s) * ldb + k0 + c1s * 8;
            const int so = r1s * kRowB + c1s * 16;
            *(uint4*)(stp + AH + so) = *(const uint4*)(pAh + ga);
            *(uint4*)(stp + BH + so) = *(const uint4*)(pBh + gb);
            if (NPROD == 3) {
                *(uint4*)(stp + AL + so) = *(const uint4*)(pAl + ga);
                *(uint4*)(stp + BL + so) = *(const uint4*)(pBl + gb);
            }
        }
    };

    stageStore(0);
    __syncthreads();

    const int laneA_row = (lane & 15);
    const int laneA_cb  = (lane >> 4) * 16;
    const int laneB_row = (lane & 7);
    const int laneB_cb  = ((lane >> 3) & 1) * 16;

    for (int c = 0; c < nCh; c++) {
        if (c + 1 < nCh) stageStore(c + 1);

        const uint32_t stb = sb + (c & 1) * STAGE;
#pragma unroll
        for (int kf = 0; kf < 2; kf++) {
            const int kb = kf * 32;
            uint32_t a_h[4][4], a_l[4][4], b_h[4][2], b_l[4][2];
#pragma unroll
            for (int i = 0; i < 4; i++) {
                const uint32_t ra = stb + (uint32_t)((wy * 64 + i * 16 + laneA_row) * kRowB + kb + laneA_cb);
                ldsm_x4(a_h[i], ra + AH);
                if (NPROD == 3) ldsm_x4(a_l[i], ra + AL);
            }
#pragma unroll
            for (int j = 0; j < 4; j++) {
                const uint32_t rb = stb + (uint32_t)((wx * 32 + j * 8 + laneB_row) * kRowB + kb + laneB_cb);
                ldsm_x2(b_h[j], rb + BH);
                if (NPROD == 3) ldsm_x2(b_l[j], rb + BL);
            }
#pragma unroll
            for (int i = 0; i < 4; i++)
#pragma unroll
                for (int j = 0; j < 4; j++) {
                    mma_bf16(acc[i][j], a_h[i], b_h[j]);
                    if (NPROD == 3) {
                        mma_bf16(acc[i][j], a_h[i], b_l[j]);
                        mma_bf16(acc[i][j], a_l[i], b_h[j]);
                    }
                }
        }
        __syncthreads();
    }

    if (KEY16) {
        uint16_t* Cb = (uint16_t*)Cv + (long long)z * cS;
#pragma unroll
        for (int i = 0; i < 4; i++) {
            const int rr = m0 + wy * 64 + i * 16 + (lane >> 2);
#pragma unroll
            for (int j = 0; j < 4; j++) {
                const int cc = n0 + wx * 32 + j * 8 + (lane & 3) * 2;
                const uint32_t k0 = (uint32_t)bf16_mono(acc[i][j][0]) | ((uint32_t)bf16_mono(acc[i][j][1]) << 16);
                const uint32_t k1 = (uint32_t)bf16_mono(acc[i][j][2]) | ((uint32_t)bf16_mono(acc[i][j][3]) << 16);
                *(uint32_t*)(Cb + (long long)rr * ldc + cc)       = k0;
                *(uint32_t*)(Cb + (long long)(rr + 8) * ldc + cc) = k1;
            }
        }
    } else {
        float* Cb = (float*)Cv + (long long)z * cS;
#pragma unroll
        for (int i = 0; i < 4; i++) {
            const int rr = m0 + wy * 64 + i * 16 + (lane >> 2);
#pragma unroll
            for (int j = 0; j < 4; j++) {
                const int cc = n0 + wx * 32 + j * 8 + (lane & 3) * 2;
                float2 v0; v0.x = acc[i][j][0]; v0.y = acc[i][j][1];
                float2 v1; v1.x = acc[i][j][2]; v1.y = acc[i][j][3];
                *(float2*)(Cb + (long long)rr * ldc + cc)       = v0;
                *(float2*)(Cb + (long long)(rr + 8) * ldc + cc) = v1;
            }
        }
    }
}

// ================= fp32 SGEMM (exact path for Q projection) =================
__global__ void __launch_bounds__(256, 2)
sgemm_nt(const float* __restrict__ A, int lda,
         const float* __restrict__ B, int ldb,
         float* __restrict__ C, int ldc, int K)
{
    __shared__ float As[16][128];
    __shared__ float Bs[16][128];

    const int tid = threadIdx.x;
    const int m0  = blockIdx.y * 128;
    const int n0  = blockIdx.x * 128;

    const int lr = tid >> 2;
    const int lc = (tid & 3) << 2;
    const int tx = tid & 15;
    const int ty = tid >> 4;

    float acc[8][8];
#pragma unroll
    for (int i = 0; i < 8; i++)
#pragma unroll
        for (int j = 0; j < 8; j++) acc[i][j] = 0.f;

    for (int k0 = 0; k0 < K; k0 += 16) {
        float4 a0 = *(const float4*)(A + (long long)(m0 + lr)      * lda + k0 + lc);
        float4 a1 = *(const float4*)(A + (long long)(m0 + lr + 64) * lda + k0 + lc);
        float4 b0 = *(const float4*)(B + (long long)(n0 + lr)      * ldb + k0 + lc);
        float4 b1 = *(const float4*)(B + (long long)(n0 + lr + 64) * ldb + k0 + lc);
        __syncthreads();
        As[lc + 0][lr] = a0.x; As[lc + 1][lr] = a0.y; As[lc + 2][lr] = a0.z; As[lc + 3][lr] = a0.w;
        As[lc + 0][lr + 64] = a1.x; As[lc + 1][lr + 64] = a1.y; As[lc + 2][lr + 64] = a1.z; As[lc + 3][lr + 64] = a1.w;
        Bs[lc + 0][lr] = b0.x; Bs[lc + 1][lr] = b0.y; Bs[lc + 2][lr] = b0.z; Bs[lc + 3][lr] = b0.w;
        Bs[lc + 0][lr + 64] = b1.x; Bs[lc + 1][lr + 64] = b1.y; Bs[lc + 2][lr + 64] = b1.z; Bs[lc + 3][lr + 64] = b1.w;
        __syncthreads();
#pragma unroll
        for (int kk = 0; kk < 16; kk++) {
            float4 av0 = *(const float4*)&As[kk][ty * 8];
            float4 av1 = *(const float4*)&As[kk][ty * 8 + 4];
            float4 bv0 = *(const float4*)&Bs[kk][tx * 8];
            float4 bv1 = *(const float4*)&Bs[kk][tx * 8 + 4];
            float a[8] = {av0.x, av0.y, av0.z, av0.w, av1.x, av1.y, av1.z, av1.w};
            float b[8] = {bv0.x, bv0.y, bv0.z, bv0.w, bv1.x, bv1.y, bv1.z, bv1.w};
#pragma unroll
            for (int i = 0; i < 8; i++)
#pragma unroll
                for (int j = 0; j < 8; j++) acc[i][j] = fmaf(a[i], b[j], acc[i][j]);
        }
    }

#pragma unroll
    for (int i = 0; i < 8; i++) {
        float* crow = C + (long long)(m0 + ty * 8 + i) * ldc + n0 + tx * 8;
#pragma unroll
        for (int j = 0; j < 8; j++) crow[j] = acc[i][j];
    }
}

// ================= splits =================
__global__ void split_kernel(const float* __restrict__ src,
                             __nv_bfloat16* __restrict__ hi,
                             __nv_bfloat16* __restrict__ lo, int n4)
{
    const int i = blockIdx.x * blockDim.x + threadIdx.x;
    if (i >= n4) return;
    const float4 v = ((const float4*)src)[i];
    __nv_bfloat16 h0 = __float2bfloat16(v.x);
    __nv_bfloat16 h1 = __float2bfloat16(v.y);
    __nv_bfloat16 h2 = __float2bfloat16(v.z);
    __nv_bfloat16 h3 = __float2bfloat16(v.w);
    __nv_bfloat162 H0; H0.x = h0; H0.y = h1;
    __nv_bfloat162 H1; H1.x = h2; H1.y = h3;
    __nv_bfloat162 L0, L1;
    L0.x = __float2bfloat16(v.x - __bfloat162float(h0));
    L0.y = __float2bfloat16(v.y - __bfloat162float(h1));
    L1.x = __float2bfloat16(v.z - __bfloat162float(h2));
    L1.y = __float2bfloat16(v.w - __bfloat162float(h3));
    ((__nv_bfloat162*)hi)[2 * i]     = H0;
    ((__nv_bfloat162*)hi)[2 * i + 1] = H1;
    ((__nv_bfloat162*)lo)[2 * i]     = L0;
    ((__nv_bfloat162*)lo)[2 * i + 1] = L1;
}

__global__ void qsplit_kernel()
{
    const int gw   = (blockIdx.x * blockDim.x + threadIdx.x) >> 5;
    const int lane = threadIdx.x & 31;
    if (gw >= kNH * kS) return;
    const int h = gw >> 9;
    const int q = gw & 511;
    float4 v = *(const float4*)(g_qkv + (long long)q * kQKVld + h * kD + lane * 4);
    float s = v.x * v.x + v.y * v.y + v.z * v.z + v.w * v.w;
#pragma unroll
    for (int o = 16; o > 0; o >>= 1) s += __shfl_xor_sync(0xffffffffu, s, o);
    const float inv = rsqrtf(s);
    v.x *= inv; v.y *= inv; v.z *= inv; v.w *= inv;
    const long long base = (long long)gw * kD + lane * 4;
    *(float4*)(g_qn_f32 + base) = v;
    __nv_bfloat162 H0, H1;
    H0.x = __float2bfloat16(v.x); H0.y = __float2bfloat16(v.y);
    H1.x = __float2bfloat16(v.z); H1.y = __float2bfloat16(v.w);
    *(__nv_bfloat162*)(g_qn_h + base)     = H0;
    *(__nv_bfloat162*)(g_qn_h + base + 2) = H1;
}

__global__ void ksplit_kernel(const float* __restrict__ kc)
{
    const int gw   = (blockIdx.x * blockDim.x + threadIdx.x) >> 5;
    const int lane = threadIdx.x & 31;
    if (gw >= kNH * kSC) return;
    float4 v = *(const float4*)(kc + (long long)gw * kD + lane * 4);
    float s = v.x * v.x + v.y * v.y + v.z * v.z + v.w * v.w;
#pragma unroll
    for (int o = 16; o > 0; o >>= 1) s += __shfl_xor_sync(0xffffffffu, s, o);
    const float inv = rsqrtf(s);
    v.x *= inv; v.y *= inv; v.z *= inv; v.w *= inv;
    const long long base = (long long)gw * kD + lane * 4;
    *(float4*)(g_kn_f32 + base) = v;
    __nv_bfloat162 H0, H1;
    H0.x = __float2bfloat16(v.x); H0.y = __float2bfloat16(v.y);
    H1.x = __float2bfloat16(v.z); H1.y = __float2bfloat16(v.w);
    *(__nv_bfloat162*)(g_kn_h + base)     = H0;
    *(__nv_bfloat162*)(g_kn_h + base + 2) = H1;
}

// ---------------- per-(h,q) approx top-32 over 8192 packed keys ----------------
// packed = key16 << 13 | (8191 - idx): one UMAX gives argmax with lowest-idx tie-break.
__global__ void __launch_bounds__(256)
topk_kernel()
{
    const long long row = blockIdx.x;  // h*512 + q
    const uint16_t* sim = g_simkey + row * kSC;
    const int tid = threadIdx.x;
    const int lane = tid & 31;
    const int w = tid >> 5;

    uint32_t v[32];
#pragma unroll
    for (int c = 0; c < 4; c++) {
        const int base = c * 2048 + tid * 8;
        uint4 raw = *(const uint4*)(sim + base);
        const uint32_t words[4] = {raw.x, raw.y, raw.z, raw.w};
#pragma unroll
        for (int j = 0; j < 4; j++) {
            const uint32_t lo = words[j] & 0xFFFFu;
            const uint32_t hi = words[j] >> 16;
            v[c * 8 + 2 * j]     = (lo << 13) | (uint32_t)(8191 - (base + 2 * j));
            v[c * 8 + 2 * j + 1] = (hi << 13) | (uint32_t)(8191 - (base + 2 * j + 1));
        }
    }

    uint32_t locmax = 0;
#pragma unroll
    for (int i = 0; i < 32; i++) locmax = max(locmax, v[i]);

    __shared__ uint32_t wv[8];
    __shared__ uint32_t bshare;

    for (int r = 0; r < kCand; r++) {
        const uint32_t wm = __reduce_max_sync(0xffffffffu, locmax);
        if (lane == 0) wv[w] = wm;
        __syncthreads();
        if (tid == 0) {
            uint32_t b = wv[0];
#pragma unroll
            for (int k = 1; k < 8; k++) b = max(b, wv[k]);
            bshare = b;
            g_cand[row * kCand + r] = 8191 - (int)(b & 8191u);
        }
        __syncthreads();
        const uint32_t best = bshare;
        if (locmax == best) {
            uint32_t nm = 0;
#pragma unroll
            for (int i = 0; i < 32; i++) {
                if (v[i] == best) v[i] = 0;
                nm = max(nm, v[i]);
            }
            locmax = nm;
        }
    }
}

// ---------------- exact rescore of 32 candidates -> exact top-16 ----------------
__global__ void __launch_bounds__(256)
rescore_kernel()
{
    const int gw   = (blockIdx.x * blockDim.x + threadIdx.x) >> 5;
    const int lane = threadIdx.x & 31;
    if (gw >= kNH * kS) return;
    const int h = gw >> 9;

    const float4 qv = *(const float4*)(g_qn_f32 + (long long)gw * kD + lane * 4);
    int   myidx = g_cand[gw * kCand + lane];
    float myval = -FLT_MAX;

    for (int c = 0; c < kCand; c++) {
        const int idx = __shfl_sync(0xffffffffu, myidx, c);
        const float4 kv = *(const float4*)(g_kn_f32 + ((long long)h * kSC + idx) * kD + lane * 4);
        float p = qv.x * kv.x + qv.y * kv.y + qv.z * kv.z + qv.w * kv.w;
#pragma unroll
        for (int o = 16; o > 0; o >>= 1) p += __shfl_xor_sync(0xffffffffu, p, o);
        if (lane == c) myval = p;
    }

    for (int r = 0; r < kTopK; r++) {
        float v = myval; int ix = myidx;
#pragma unroll
        for (int o = 16; o > 0; o >>= 1) {
            float ov = __shfl_xor_sync(0xffffffffu, v, o);
            int   oi = __shfl_xor_sync(0xffffffffu, ix, o);
            if (ov > v || (ov == v && oi < ix)) { v = ov; ix = oi; }
        }
        if (lane == 0) {
            g_topv[gw * kTopK + r] = v;
            g_topi[gw * kTopK + r] = ix;
        }
        if (myidx == ix) myval = -FLT_MAX;
    }
}

// ---------------- fused attention per (h,q) (round-5 proven version) ----------------
__global__ void __launch_bounds__(256)
attn_kernel(const float* __restrict__ kc, const float* __restrict__ vc,
            const float* __restrict__ bias)
{
    const int q = blockIdx.x;
    const int h = blockIdx.y;
    const int tid = threadIdx.x;
    const int lane = tid & 31;
    const int w = tid >> 5;

    __shared__ float qs[128];
    __shared__ float ssc[16 + kS];
    __shared__ int   sidx[16];
    __shared__ float redw[8];
    __shared__ float bmax, bsuminv;
    __shared__ float ctx2[128];

    const long long rowhq = (long long)h * kS + q;

    if (tid < 128) qs[tid] = g_qkv[(long long)q * kQKVld + h * kD + tid];
    if (tid < 16)  sidx[tid] = g_topi[rowhq * 16 + tid];
    __syncthreads();

    const float4 qv = *(const float4*)(qs + lane * 4);

    for (int j = w; j < 16; j += 8) {
        float s;
        if (g_topv[rowhq * 16 + j] > kSimTh) {
            const float* kp = kc + ((long long)h * kSC + sidx[j]) * kD;
            float4 kv = *(const float4*)(kp + lane * 4);
            float p = qv.x * kv.x + qv.y * kv.y + qv.z * kv.z + qv.w * kv.w;
#pragma unroll
            for (int o = 16; o > 0; o >>= 1) p += __shfl_down_sync(0xffffffffu, p, o);
            s = p * kScale;
        } else {
            s = kNeg;
        }
        if (lane == 0) ssc[j] = s;
    }

    const float* biasrow = bias + ((long long)h * kS + q) * kS;
    for (int kk = w; kk < kS; kk += 8) {
        float s;
        if (kk <= q) {
            const float* kp = g_qkv + (long long)kk * kQKVld + kH + h * kD;
            float4 kv = *(const float4*)(kp + lane * 4);
            float p = qv.x * kv.x + qv.y * kv.y + qv.z * kv.z + qv.w * kv.w;
#pragma unroll
            for (int o = 16; o > 0; o >>= 1) p += __shfl_down_sync(0xffffffffu, p, o);
            s = p * kScale + biasrow[kk];
        } else {
            s = kNeg;
        }
        if (lane == 0) ssc[16 + kk] = s;
    }
    __syncthreads();

    float m = -FLT_MAX;
    for (int j = tid; j < 16 + kS; j += 256) m = fmaxf(m, ssc[j]);
#pragma unroll
    for (int o = 16; o > 0; o >>= 1) m = fmaxf(m, __shfl_down_sync(0xffffffffu, m, o));
    if (lane == 0) redw[w] = m;
    __syncthreads();
    if (tid == 0) {
        float mm = redw[0];
#pragma unroll
        for (int k = 1; k < 8; k++) mm = fmaxf(mm, redw[k]);
        bmax = mm;
    }
    __syncthreads();
    const float msc = bmax;
    float ss = 0.f;
    for (int j = tid; j < 16 + kS; j += 256) {
        float e = __expf(ssc[j] - msc);
        ssc[j] = e;
        ss += e;
    }
#pragma unroll
    for (int o = 16; o > 0; o >>= 1) ss += __shfl_down_sync(0xffffffffu, ss, o);
    if (lane == 0) redw[w] = ss;
    __syncthreads();
    if (tid == 0) {
        float t = 0.f;
#pragma unroll
        for (int k = 0; k < 8; k++) t += redw[k];
        bsuminv = 1.f / t;
    }
    __syncthreads();

    const int g = tid >> 7;
    const int d = tid & 127;
    float acc = 0.f;
    for (int j = g; j < 16; j += 2) {
        float p = ssc[j];
        if (p > 0.f) acc += p * vc[((long long)h * kSC + sidx[j]) * kD + d];
    }
    for (int kk = g; kk <= q; kk += 2) {
        acc += ssc[16 + kk] * g_qkv[(long long)kk * kQKVld + 2 * kH + h * kD + d];
    }
    if (g == 1) ctx2[d] = acc;
    __syncthreads();
    if (g == 0) {
        g_ctx[(long long)q * kH + h * kD + d] = (acc + ctx2[d]) * bsuminv;
    }
}

// ---------------- launcher ----------------
extern "C" void kernel_launch(void* const* d_in, const int* in_sizes, int n_in,
                              void* d_out, int out_size)
{
    const float* hidden = (const float*)d_in[0];
    const float* Wqkv   = (const float*)d_in[1];
    const float* Wout   = (const float*)d_in[2];
    const float* kc     = (const float*)d_in[3];
    const float* vc     = (const float*)d_in[4];
    const float* bias   = (const float*)d_in[5];
    float* out = (float*)d_out;

    float *p_qkv, *p_ctx;
    uint16_t* p_simkey;
    cudaGetSymbolAddress((void**)&p_qkv,  g_qkv);
    cudaGetSymbolAddress((void**)&p_simkey, g_simkey);
    cudaGetSymbolAddress((void**)&p_ctx,  g_ctx);
    __nv_bfloat16 *p_hid_h, *p_hid_l, *p_wqkv_h, *p_wqkv_l, *p_wout_h, *p_wout_l;
    __nv_bfloat16 *p_qn_h, *p_kn_h, *p_ctx_h, *p_ctx_l;
    cudaGetSymbolAddress((void**)&p_hid_h,  g_hid_h);
    cudaGetSymbolAddress((void**)&p_hid_l,  g_hid_l);
    cudaGetSymbolAddress((void**)&p_wqkv_h, g_wqkv_h);
    cudaGetSymbolAddress((void**)&p_wqkv_l, g_wqkv_l);
    cudaGetSymbolAddress((void**)&p_wout_h, g_wout_h);
    cudaGetSymbolAddress((void**)&p_wout_l, g_wout_l);
    cudaGetSymbolAddress((void**)&p_qn_h,   g_qn_h);
    cudaGetSymbolAddress((void**)&p_kn_h,   g_kn_h);
    cudaGetSymbolAddress((void**)&p_ctx_h,  g_ctx_h);
    cudaGetSymbolAddress((void**)&p_ctx_l,  g_ctx_l);

    cudaFuncSetAttribute((const void*)mma_gemm<3, false>, cudaFuncAttributeMaxDynamicSharedMemorySize, 2 * 4 * kMatB);
    cudaFuncSetAttribute((const void*)mma_gemm<1, true>,  cudaFuncAttributeMaxDynamicSharedMemorySize, 2 * 2 * kMatB);

    // 1. splits of weights / hidden + normalized k cache (fp32 + bf16)
    split_kernel<<<(kQKVld * kH / 4 + 255) / 256, 256>>>(Wqkv, p_wqkv_h, p_wqkv_l, kQKVld * kH / 4);
    split_kernel<<<(kH * kH / 4 + 255) / 256, 256>>>(Wout, p_wout_h, p_wout_l, kH * kH / 4);
    split_kernel<<<(kS * kH / 4 + 255) / 256, 256>>>(hidden, p_hid_h, p_hid_l, kS * kH / 4);
    ksplit_kernel<<<(kNH * kSC * 32) / 256, 256>>>(kc);

    // 2a. Q projection EXACT fp32
    sgemm_nt<<<dim3(kH / 128, kS / 128), 256>>>(hidden, kH, Wqkv, kH, p_qkv, kQKVld, kH);

    // 2b. K,V projections (HMMA 3-prod)
    mma_gemm<3, false><<<dim3(4096 / 128, kS / 128, 1), 256, 2 * 4 * kMatB>>>(
        p_hid_h, p_hid_l, p_wqkv_h + (size_t)2048 * kH, p_wqkv_l + (size_t)2048 * kH,
        p_qkv + 2048, kH, kH, kQKVld, 0, 0, 0, kH);

    // 3. normalized q (fp32 + bf16)
    qsplit_kernel<<<(kNH * kS * 32) / 256, 256>>>();

    // 4. approx cosine-sim GEMM -> 16-bit monotone keys
    mma_gemm<1, true><<<dim3(kSC / 128, kS / 128, kNH), 256, 2 * 2 * kMatB>>>(
        p_qn_h, nullptr, p_kn_h, nullptr, p_simkey,
        kD, kD, kSC,
        (long long)kS * kD, (long long)kSC * kD, (long long)kS * kSC, kD);

    // 5. approx top-32 candidate pool per (h,q) (packed-key tournament)
    topk_kernel<<<kNH * kS, 256>>>();

    // 6. exact fp32 rescore -> exact top-16
    rescore_kernel<<<(kNH * kS * 32 + 255) / 256, 256>>>();

    // 7. fused attention (round-5 version) -> g_ctx
    attn_kernel<<<dim3(kS, kNH), 256>>>(kc, vc, bias);

    // 8. ctx split + output projection (HMMA 3-prod)
    split_kernel<<<(kS * kH / 4 + 255) / 256, 256>>>(p_ctx, p_ctx_h, p_ctx_l, kS * kH / 4);
    mma_gemm<3, false><<<dim3(kH / 128, kS / 128, 1), 256, 2 * 4 * kMatB>>>(
        p_ctx_h, p_ctx_l, p_wout_h, p_wout_l, out,
        kH, kH, kH, 0, 0, 0, kH);
}